// round 6
// baseline (speedup 1.0000x reference)
#include <cuda_runtime.h>

#define NPTS    2048
#define THREADS 256
#define SLICES  32                 // j-slices per i (full warp)
#define GRPS    (THREADS/SLICES)   // 8 warps per CTA
#define IPB     (GRPS*2)           // 16 i's per CTA (2 per thread)
#define EPS     1e-5f
#define WBIAS   1e-6f              // w-lane bias: sq gets +1e-12 (diagonal-safe)

typedef unsigned long long ull;

__device__ __forceinline__ ull pack2(float x, float y) {
    ull v; asm("mov.b64 %0, {%1,%2};" : "=l"(v) : "f"(x), "f"(y)); return v;
}
__device__ __forceinline__ float2 unpack2(ull v) {
    float2 r; asm("mov.b64 {%0,%1}, %2;" : "=f"(r.x), "=f"(r.y) : "l"(v)); return r;
}
__device__ __forceinline__ ull fma2(ull a, ull b, ull c) {
    ull d; asm("fma.rn.f32x2 %0, %1, %2, %3;" : "=l"(d) : "l"(a), "l"(b), "l"(c)); return d;
}
__device__ __forceinline__ ull mul2(ull a, ull b) {
    ull d; asm("mul.rn.f32x2 %0, %1, %2;" : "=l"(d) : "l"(a), "l"(b)); return d;
}

__global__ __launch_bounds__(THREADS) void spring_kernel(
    const float* __restrict__ X, const float* __restrict__ Kp,
    const float* __restrict__ Bp, float* __restrict__ out)
{
    __shared__ float4 xs[NPTS];
    __shared__ float4 red[THREADS / 32];
    const int b   = blockIdx.y;
    const int tid = threadIdx.x;
    const float* Xb = X + (size_t)b * NPTS * 3;

    // Stage batch into SMEM as (x, y, z, 0) + partial sums for S = sum_j x_j.
    float sx = 0.f, sy = 0.f, sz = 0.f;
    for (int p = tid; p < NPTS; p += THREADS) {
        float4 v = make_float4(Xb[3*p], Xb[3*p+1], Xb[3*p+2], 0.f);
        xs[p] = v;
        sx += v.x; sy += v.y; sz += v.z;
    }
    #pragma unroll
    for (int m = 16; m >= 1; m >>= 1) {
        sx += __shfl_xor_sync(0xffffffffu, sx, m);
        sy += __shfl_xor_sync(0xffffffffu, sy, m);
        sz += __shfl_xor_sync(0xffffffffu, sz, m);
    }
    if ((tid & 31) == 0) red[tid >> 5] = make_float4(sx, sy, sz, 0.f);
    __syncthreads();
    float4 S = make_float4(0.f, 0.f, 0.f, 0.f);
    #pragma unroll
    for (int wdx = 0; wdx < THREADS / 32; wdx++) {
        S.x += red[wdx].x; S.y += red[wdx].y; S.z += red[wdx].z;
    }

    const float K = *Kp;
    const float c = K * (*Bp + EPS);   // f = K - c*w,  w ~= 1/(dist+eps) ~= rsqrt(sq)

    const int grp   = tid / SLICES;    // warp id, 0..7
    const int slice = tid % SLICES;    // lane
    const int i0 = blockIdx.x * IPB + grp;
    const int i1 = i0 + GRPS;

    const float4 p0 = xs[i0];
    const float4 p1 = xs[i1];
    const ull p0xy  = pack2(p0.x, p0.y);
    const ull p1xy  = pack2(p1.x, p1.y);
    const ull p0zw  = pack2(p0.z, WBIAS);   // bias lane -> sq += 1e-12
    const ull p1zw  = pack2(p1.z, WBIAS);
    const ull neg1  = pack2(-1.f, -1.f);

    ull h0xy = pack2(0.f, 0.f), h1xy = pack2(0.f, 0.f);
    ull h0zw = pack2(0.f, 0.f), h1zw = pack2(0.f, 0.f);   // w lane = junk

    // Each warp's 32 lanes read 32 consecutive float4s: conflict-free LDS.128.
    // One load feeds 2 independent i-chains.
    #pragma unroll 4
    for (int j = slice; j < NPTS; j += SLICES) {
        const float4 pj = xs[j];
        const ull pjxy  = pack2(pj.x, pj.y);
        const ull pjzw  = pack2(pj.z, 0.f);

        // pair (i0, j)
        {
            const ull dxy = fma2(pjxy, neg1, p0xy);      // (dx, dy)
            const ull dzw = fma2(pjzw, neg1, p0zw);      // (dz, 1e-6)
            const ull s2  = fma2(dzw, dzw, mul2(dxy, dxy)); // (dx2+dz2, dy2+1e-12)
            const float2 t = unpack2(s2);
            const float r  = rsqrtf(t.x + t.y);          // finite on diagonal
            const ull r2   = pack2(r, r);
            h0xy = fma2(r2, dxy, h0xy);
            h0zw = fma2(r2, dzw, h0zw);
        }
        // pair (i1, j)
        {
            const ull dxy = fma2(pjxy, neg1, p1xy);
            const ull dzw = fma2(pjzw, neg1, p1zw);
            const ull s2  = fma2(dzw, dzw, mul2(dxy, dxy));
            const float2 t = unpack2(s2);
            const float r  = rsqrtf(t.x + t.y);
            const ull r2   = pack2(r, r);
            h1xy = fma2(r2, dxy, h1xy);
            h1zw = fma2(r2, dzw, h1zw);
        }
    }

    float2 h0 = unpack2(h0xy);
    float2 h1 = unpack2(h1xy);
    float v0 = h0.x, v1 = h0.y, v2 = unpack2(h0zw).x;
    float v3 = h1.x, v4 = h1.y, v5 = unpack2(h1zw).x;

    // Reduce the 32 j-slices across the warp.
    #pragma unroll
    for (int m = 1; m < SLICES; m <<= 1) {
        v0 += __shfl_xor_sync(0xffffffffu, v0, m);
        v1 += __shfl_xor_sync(0xffffffffu, v1, m);
        v2 += __shfl_xor_sync(0xffffffffu, v2, m);
        v3 += __shfl_xor_sync(0xffffffffu, v3, m);
        v4 += __shfl_xor_sync(0xffffffffu, v4, m);
        v5 += __shfl_xor_sync(0xffffffffu, v5, m);
    }

    if (slice == 0) {
        // out = x_i + K*(N*x_i - S) - c*h
        float* o0 = out + ((size_t)b * NPTS + i0) * 3;
        o0[0] = fmaf(K, fmaf((float)NPTS, p0.x, -S.x), fmaf(-c, v0, p0.x));
        o0[1] = fmaf(K, fmaf((float)NPTS, p0.y, -S.y), fmaf(-c, v1, p0.y));
        o0[2] = fmaf(K, fmaf((float)NPTS, p0.z, -S.z), fmaf(-c, v2, p0.z));
        float* o1 = out + ((size_t)b * NPTS + i1) * 3;
        o1[0] = fmaf(K, fmaf((float)NPTS, p1.x, -S.x), fmaf(-c, v3, p1.x));
        o1[1] = fmaf(K, fmaf((float)NPTS, p1.y, -S.y), fmaf(-c, v4, p1.y));
        o1[2] = fmaf(K, fmaf((float)NPTS, p1.z, -S.z), fmaf(-c, v5, p1.z));
    }
}

extern "C" void kernel_launch(void* const* d_in, const int* in_sizes, int n_in,
                              void* d_out, int out_size) {
    const float* X = (const float*)d_in[0];
    const float* K = (const float*)d_in[1];
    const float* B = (const float*)d_in[2];
    float* out = (float*)d_out;

    const int batch = in_sizes[0] / (NPTS * 3);
    dim3 grid(NPTS / IPB, batch);
    spring_kernel<<<grid, THREADS>>>(X, K, B, out);
}

// round 7
// speedup vs baseline: 1.0135x; 1.0135x over previous
#include <cuda_runtime.h>

#define NPTS    2048
#define THREADS 256
#define SLICES  32                 // j-slices per i (full warp)
#define GRPS    (THREADS/SLICES)   // 8 warps per CTA
#define NI      4                  // i's per thread
#define IPB     (GRPS*NI)          // 32 i's per CTA
#define EPS     1e-5f
#define WBIAS   1e-6f              // w-lane bias: sq gets +1e-12 (diagonal-safe)

typedef unsigned long long ull;

__device__ __forceinline__ ull pack2(float x, float y) {
    ull v; asm("mov.b64 %0, {%1,%2};" : "=l"(v) : "f"(x), "f"(y)); return v;
}
__device__ __forceinline__ float2 unpack2(ull v) {
    float2 r; asm("mov.b64 {%0,%1}, %2;" : "=f"(r.x), "=f"(r.y) : "l"(v)); return r;
}
__device__ __forceinline__ ull fma2(ull a, ull b, ull c) {
    ull d; asm("fma.rn.f32x2 %0, %1, %2, %3;" : "=l"(d) : "l"(a), "l"(b), "l"(c)); return d;
}
__device__ __forceinline__ ull mul2(ull a, ull b) {
    ull d; asm("mul.rn.f32x2 %0, %1, %2;" : "=l"(d) : "l"(a), "l"(b)); return d;
}
__device__ __forceinline__ ull add2(ull a, ull b) {
    ull d; asm("add.rn.f32x2 %0, %1, %2;" : "=l"(d) : "l"(a), "l"(b)); return d;
}

__global__ __launch_bounds__(THREADS) void spring_kernel(
    const float* __restrict__ X, const float* __restrict__ Kp,
    const float* __restrict__ Bp, float* __restrict__ out)
{
    __shared__ float4 xs[NPTS];
    __shared__ float4 red[THREADS / 32];
    const int b   = blockIdx.y;
    const int tid = threadIdx.x;
    const float* Xb = X + (size_t)b * NPTS * 3;

    // Stage batch into SMEM as (x, y, z, 0) + partial sums for S = sum_j x_j.
    float sx = 0.f, sy = 0.f, sz = 0.f;
    for (int p = tid; p < NPTS; p += THREADS) {
        float4 v = make_float4(Xb[3*p], Xb[3*p+1], Xb[3*p+2], 0.f);
        xs[p] = v;
        sx += v.x; sy += v.y; sz += v.z;
    }
    #pragma unroll
    for (int m = 16; m >= 1; m >>= 1) {
        sx += __shfl_xor_sync(0xffffffffu, sx, m);
        sy += __shfl_xor_sync(0xffffffffu, sy, m);
        sz += __shfl_xor_sync(0xffffffffu, sz, m);
    }
    if ((tid & 31) == 0) red[tid >> 5] = make_float4(sx, sy, sz, 0.f);
    __syncthreads();
    float4 S = make_float4(0.f, 0.f, 0.f, 0.f);
    #pragma unroll
    for (int wdx = 0; wdx < THREADS / 32; wdx++) {
        S.x += red[wdx].x; S.y += red[wdx].y; S.z += red[wdx].z;
    }

    const float K = *Kp;
    const float c = K * (*Bp + EPS);   // f = K - c*w,  w ~= rsqrt(sq)

    const int grp   = tid / SLICES;    // warp id, 0..7
    const int slice = tid % SLICES;    // lane
    const int ib = blockIdx.x * IPB + grp;

    // 4 i's per thread, GRPS apart.
    ull pxy[NI], pzw[NI], hxy[NI], hzw[NI];
    float4 pi[NI];
    #pragma unroll
    for (int q = 0; q < NI; q++) {
        pi[q]  = xs[ib + q * GRPS];
        pxy[q] = pack2(pi[q].x, pi[q].y);
        pzw[q] = pack2(pi[q].z, WBIAS);     // bias lane -> sq += 1e-12
        hxy[q] = pack2(0.f, 0.f);
        hzw[q] = pack2(0.f, 0.f);           // w lane accumulates junk
    }
    const ull neg1 = pack2(-1.f, -1.f);

    // 32 lanes read 32 consecutive float4s: conflict-free LDS.128.
    // One load feeds 4 independent i-chains (ILP=4, LDS amortized 4x).
    #pragma unroll 4
    for (int j = slice; j < NPTS; j += SLICES) {
        const float4 pj = xs[j];
        const ull pjxy  = pack2(pj.x, pj.y);
        const ull pjzw  = pack2(pj.z, 0.f);

        #pragma unroll
        for (int q = 0; q < NI; q++) {
            const ull dxy = fma2(pjxy, neg1, pxy[q]);       // (dx, dy)
            const ull dzw = fma2(pjzw, neg1, pzw[q]);       // (dz, 1e-6)
            const ull s2  = fma2(dzw, dzw, mul2(dxy, dxy)); // (dx2+dz2, dy2+1e-12)
            const float2 t = unpack2(s2);
            const float r  = rsqrtf(t.x + t.y);             // finite on diagonal
            const ull r2   = pack2(r, r);
            hxy[q] = fma2(r2, dxy, hxy[q]);
            hzw[q] = fma2(r2, dzw, hzw[q]);
        }
    }

    // Packed warp reduction over the 32 j-slices.
    #pragma unroll
    for (int m = 1; m < SLICES; m <<= 1) {
        #pragma unroll
        for (int q = 0; q < NI; q++) {
            hxy[q] = add2(hxy[q], __shfl_xor_sync(0xffffffffu, hxy[q], m));
            hzw[q] = add2(hzw[q], __shfl_xor_sync(0xffffffffu, hzw[q], m));
        }
    }

    if (slice == 0) {
        #pragma unroll
        for (int q = 0; q < NI; q++) {
            const float2 hq = unpack2(hxy[q]);
            const float  hz = unpack2(hzw[q]).x;
            const int i = ib + q * GRPS;
            float* o = out + ((size_t)b * NPTS + i) * 3;
            // out = x_i + K*(N*x_i - S) - c*h
            o[0] = fmaf(K, fmaf((float)NPTS, pi[q].x, -S.x), fmaf(-c, hq.x, pi[q].x));
            o[1] = fmaf(K, fmaf((float)NPTS, pi[q].y, -S.y), fmaf(-c, hq.y, pi[q].y));
            o[2] = fmaf(K, fmaf((float)NPTS, pi[q].z, -S.z), fmaf(-c, hz,   pi[q].z));
        }
    }
}

extern "C" void kernel_launch(void* const* d_in, const int* in_sizes, int n_in,
                              void* d_out, int out_size) {
    const float* X = (const float*)d_in[0];
    const float* K = (const float*)d_in[1];
    const float* B = (const float*)d_in[2];
    float* out = (float*)d_out;

    const int batch = in_sizes[0] / (NPTS * 3);
    dim3 grid(NPTS / IPB, batch);
    spring_kernel<<<grid, THREADS>>>(X, K, B, out);
}

// round 8
// speedup vs baseline: 1.2718x; 1.2548x over previous
#include <cuda_runtime.h>

#define NPTS    2048
#define THREADS 256
#define SLICES  32                 // j-slices per i (full warp)
#define GRPS    (THREADS/SLICES)   // 8 warps per CTA
#define NI      4                  // i's per thread (4 independent chains)
#define IPB     (GRPS*NI)          // 32 i's per CTA
#define EPS     1e-5f
#define TINY    1e-12f             // diagonal-safe sq bias

__global__ __launch_bounds__(THREADS, 2) void spring_kernel(
    const float* __restrict__ X, const float* __restrict__ Kp,
    const float* __restrict__ Bp, float* __restrict__ out)
{
    __shared__ float4 xs[NPTS];
    __shared__ float4 red[THREADS / 32];
    const int b   = blockIdx.y;
    const int tid = threadIdx.x;
    const float* Xb = X + (size_t)b * NPTS * 3;

    // Stage batch into SMEM as (x, y, z, 0) + partial sums for S = sum_j x_j.
    float sx = 0.f, sy = 0.f, sz = 0.f;
    for (int p = tid; p < NPTS; p += THREADS) {
        float4 v = make_float4(Xb[3*p], Xb[3*p+1], Xb[3*p+2], 0.f);
        xs[p] = v;
        sx += v.x; sy += v.y; sz += v.z;
    }
    #pragma unroll
    for (int m = 16; m >= 1; m >>= 1) {
        sx += __shfl_xor_sync(0xffffffffu, sx, m);
        sy += __shfl_xor_sync(0xffffffffu, sy, m);
        sz += __shfl_xor_sync(0xffffffffu, sz, m);
    }
    if ((tid & 31) == 0) red[tid >> 5] = make_float4(sx, sy, sz, 0.f);
    __syncthreads();
    float4 S = make_float4(0.f, 0.f, 0.f, 0.f);
    #pragma unroll
    for (int wdx = 0; wdx < THREADS / 32; wdx++) {
        S.x += red[wdx].x; S.y += red[wdx].y; S.z += red[wdx].z;
    }

    const float K = *Kp;
    const float c = K * (*Bp + EPS);   // f = K - c*w,  w ~= rsqrt(sq)

    const int grp   = tid / SLICES;    // warp id, 0..7
    const int slice = tid % SLICES;    // lane
    const int ib = blockIdx.x * IPB + grp;

    // 4 i's per thread, GRPS apart. Pure scalar state: no pairing constraints.
    float pix[NI], piy[NI], piz[NI];
    float hx[NI], hy[NI], hz[NI];
    #pragma unroll
    for (int q = 0; q < NI; q++) {
        float4 v = xs[ib + q * GRPS];
        pix[q] = v.x; piy[q] = v.y; piz[q] = v.z;
        hx[q] = 0.f; hy[q] = 0.f; hz[q] = 0.f;
    }

    // 32 lanes read 32 consecutive float4s: conflict-free LDS.128.
    // One load feeds 4 independent scalar chains; ptxas free to interleave.
    #pragma unroll 4
    for (int j = slice; j < NPTS; j += SLICES) {
        const float4 pj = xs[j];
        #pragma unroll
        for (int q = 0; q < NI; q++) {
            const float dx = pix[q] - pj.x;
            const float dy = piy[q] - pj.y;
            const float dz = piz[q] - pj.z;
            float sq = fmaf(dx, dx, TINY);      // bias folded: diagonal-safe
            sq = fmaf(dy, dy, sq);
            sq = fmaf(dz, dz, sq);
            const float r = rsqrtf(sq);         // w ~= 1/(dist+eps), err < 1e-3
            hx[q] = fmaf(r, dx, hx[q]);
            hy[q] = fmaf(r, dy, hy[q]);
            hz[q] = fmaf(r, dz, hz[q]);
        }
    }

    // Warp reduction over the 32 j-slices.
    #pragma unroll
    for (int m = 1; m < SLICES; m <<= 1) {
        #pragma unroll
        for (int q = 0; q < NI; q++) {
            hx[q] += __shfl_xor_sync(0xffffffffu, hx[q], m);
            hy[q] += __shfl_xor_sync(0xffffffffu, hy[q], m);
            hz[q] += __shfl_xor_sync(0xffffffffu, hz[q], m);
        }
    }

    if (slice == 0) {
        #pragma unroll
        for (int q = 0; q < NI; q++) {
            const int i = ib + q * GRPS;
            float* o = out + ((size_t)b * NPTS + i) * 3;
            // out = x_i + K*(N*x_i - S) - c*h
            o[0] = fmaf(K, fmaf((float)NPTS, pix[q], -S.x), fmaf(-c, hx[q], pix[q]));
            o[1] = fmaf(K, fmaf((float)NPTS, piy[q], -S.y), fmaf(-c, hy[q], piy[q]));
            o[2] = fmaf(K, fmaf((float)NPTS, piz[q], -S.z), fmaf(-c, hz[q], piz[q]));
        }
    }
}

extern "C" void kernel_launch(void* const* d_in, const int* in_sizes, int n_in,
                              void* d_out, int out_size) {
    const float* X = (const float*)d_in[0];
    const float* K = (const float*)d_in[1];
    const float* B = (const float*)d_in[2];
    float* out = (float*)d_out;

    const int batch = in_sizes[0] / (NPTS * 3);
    dim3 grid(NPTS / IPB, batch);
    spring_kernel<<<grid, THREADS>>>(X, K, B, out);
}